// round 4
// baseline (speedup 1.0000x reference)
#include <cuda_runtime.h>
#include <math.h>

#define Bb   2
#define Ll   1024
#define Dd   256
#define Kk   64
#define K2   128          // 2K (re|im concat)
#define NTOK (Bb*Ll)      // 2048
#define CH   128          // scan chunk length
#define NC   (Ll/CH)      // 8
#define NCH  (Bb*NC)      // 16
#define EPSv 1e-5f
#define PIv  3.14159265358979323846f

// ------------------------- scratch (static device memory) -------------------
__device__ float g_xa_k[NTOK*Dd];
__device__ float g_xa_q[NTOK*Dd];
__device__ float g_hk  [NTOK*Dd];
__device__ float g_hq  [NTOK*Dd];
__device__ float g_pk  [NTOK*Kk];
__device__ float g_ak  [NTOK*Kk];
__device__ float g_pq  [NTOK*Kk];
__device__ float g_aq  [NTOK*Kk];
__device__ float g_kk  [NTOK*K2];
__device__ float g_qq  [NTOK*K2];
__device__ float g_V   [NTOK*Dd];
__device__ float g_G   [NCH*K2*Dd];
__device__ float g_S   [NCH*K2*Dd];
__device__ float g_A   [NCH*CH*CH];
__device__ float g_ret [NTOK*Dd];
__device__ float g_rn  [NTOK*Dd];

// ------------------------- generic tiled SGEMM ------------------------------
// C[M,N] = epi(A @ B)  with optional transposes on operand addressing.
// TA=false: A[m,k] = A[m*Kd+k]      TA=true: A[m,k] = A[k*M+m]
// TB=false: B[k,n] = B[k*N+n]       TB=true: B[k,n] = B[n*Kd+k]
// 64x64 block tile, 16 k-slice, 256 threads, 4x4 microtile.
// gridDim.z = batch with strides sA/sB/sC.
enum { M_PLAIN = 0, M_BIAS = 1, M_GELU = 2, M_ACC = 3, M_MASK = 4, M_RESID = 5 };

template<int MODE, bool TA, bool TB>
__global__ void gemm_kernel(const float* __restrict__ A, const float* __restrict__ Bm,
                            const float* __restrict__ bias, const float* __restrict__ extra,
                            float* __restrict__ C,
                            int M, int N, int Kd,
                            long sA, long sB, long sC)
{
    A  += (long)blockIdx.z * sA;
    Bm += (long)blockIdx.z * sB;
    C  += (long)blockIdx.z * sC;
    if (MODE == M_RESID && extra) extra += (long)blockIdx.z * sC;

    __shared__ float As[16][65];
    __shared__ float Bs[16][65];

    const int tid = threadIdx.x;           // 0..255
    const int tr  = tid >> 4;              // 0..15
    const int tc  = tid & 15;              // 0..15
    const int rowTile = blockIdx.y * 64;
    const int colTile = blockIdx.x * 64;

    float acc[4][4] = {};

    for (int k0 = 0; k0 < Kd; k0 += 16) {
        #pragma unroll
        for (int t = 0; t < 4; t++) {
            int idx = tid + t * 256;       // 0..1023 covers 64x16
            int m = idx >> 4, k = idx & 15;
            As[k][m] = TA ? A[(long)(k0 + k) * M + rowTile + m]
                          : A[(long)(rowTile + m) * Kd + k0 + k];
        }
        #pragma unroll
        for (int t = 0; t < 4; t++) {
            int idx = tid + t * 256;
            if (!TB) {
                int k = idx >> 6, n = idx & 63;
                Bs[k][n] = Bm[(long)(k0 + k) * N + colTile + n];
            } else {
                int k = idx & 15, n = idx >> 4;
                Bs[k][n] = Bm[(long)(colTile + n) * Kd + k0 + k];
            }
        }
        __syncthreads();
        #pragma unroll
        for (int k = 0; k < 16; k++) {
            float a[4], b[4];
            #pragma unroll
            for (int i = 0; i < 4; i++) a[i] = As[k][tr + 16 * i];
            #pragma unroll
            for (int j = 0; j < 4; j++) b[j] = Bs[k][tc + 16 * j];
            #pragma unroll
            for (int i = 0; i < 4; i++)
                #pragma unroll
                for (int j = 0; j < 4; j++)
                    acc[i][j] = fmaf(a[i], b[j], acc[i][j]);
        }
        __syncthreads();
    }

    #pragma unroll
    for (int i = 0; i < 4; i++) {
        int r = rowTile + tr + 16 * i;
        #pragma unroll
        for (int j = 0; j < 4; j++) {
            int c = colTile + tc + 16 * j;
            float v = acc[i][j];
            if (MODE == M_BIAS || MODE == M_GELU || MODE == M_RESID) v += bias[c];
            if (MODE == M_GELU) v = 0.5f * v * (1.0f + erff(v * 0.70710678118654752440f));
            if (MODE == M_MASK) { if (c > r) v = 0.0f; }
            long o = (long)r * N + c;
            if (MODE == M_ACC)        C[o] += v;
            else if (MODE == M_RESID) C[o] = extra[o] + v;
            else                      C[o] = v;
        }
    }
}

// ------------------------- elementwise kernels ------------------------------
__global__ void addpos_kernel(const float* __restrict__ x,
                              const float* __restrict__ pos_k,
                              const float* __restrict__ pos_q)
{
    long i = (long)blockIdx.x * blockDim.x + threadIdx.x;
    if (i >= (long)NTOK * Dd) return;
    int ld = (int)(i % ((long)Ll * Dd));   // l*D + d within one batch
    float xv = x[i];
    g_xa_k[i] = xv + pos_k[ld];
    g_xa_q[i] = xv + pos_q[ld];
}

__global__ void phasor_kernel(const float* __restrict__ praw,
                              const float* __restrict__ araw,
                              float* __restrict__ out)   // [NTOK, 2K]: [cos | sin]
{
    int i = blockIdx.x * blockDim.x + threadIdx.x;
    if (i >= NTOK * Kk) return;
    int n = i / Kk, k = i % Kk;
    float ph = tanhf(praw[i]) * PIv;
    float a  = araw[i];
    float sp = fmaxf(a, 0.0f) + log1pf(expf(-fabsf(a)));   // stable softplus
    float amp = sp + 0.1f;
    float s, c;
    sincosf(ph, &s, &c);
    out[(long)n * K2 + k]      = amp * c;
    out[(long)n * K2 + Kk + k] = amp * s;
}

// exclusive prefix over the NC chunk states: S[b,c] = sum_{c'<c} G[b,c']
__global__ void prefix_kernel()
{
    const int KD = K2 * Dd;   // 32768
    int i = blockIdx.x * blockDim.x + threadIdx.x;
    if (i >= Bb * KD) return;
    int b = i / KD, r = i % KD;
    float acc = 0.0f;
    #pragma unroll
    for (int c = 0; c < NC; c++) {
        long o = ((long)(b * NC + c)) * KD + r;
        g_S[o] = acc;
        acc += g_G[o];
    }
}

// normalize by sqrt((l+1)*K), layernorm
__global__ void ln_kernel(const float* __restrict__ ret,
                          const float* __restrict__ gg,
                          const float* __restrict__ bb,
                          float* __restrict__ rn)
{
    int n = blockIdx.x;
    int l = n % Ll;
    int d = threadIdx.x;      // 256 threads == D
    float v = ret[(long)n * Dd + d] * rsqrtf((float)(l + 1) * (float)Kk);

    float s = v, s2 = v * v;
    #pragma unroll
    for (int o = 16; o; o >>= 1) {
        s  += __shfl_xor_sync(0xffffffffu, s,  o);
        s2 += __shfl_xor_sync(0xffffffffu, s2, o);
    }
    __shared__ float ss[8], ss2[8];
    int w = d >> 5, lane = d & 31;
    if (lane == 0) { ss[w] = s; ss2[w] = s2; }
    __syncthreads();
    if (w == 0) {
        float a  = (lane < 8) ? ss[lane]  : 0.0f;
        float a2 = (lane < 8) ? ss2[lane] : 0.0f;
        #pragma unroll
        for (int o = 4; o; o >>= 1) {
            a  += __shfl_xor_sync(0xffffffffu, a,  o);
            a2 += __shfl_xor_sync(0xffffffffu, a2, o);
        }
        if (lane == 0) { ss[0] = a; ss2[0] = a2; }
    }
    __syncthreads();
    float mu  = ss[0] / Dd;
    float var = ss2[0] / Dd - mu * mu;
    rn[(long)n * Dd + d] = (v - mu) * rsqrtf(var + EPSv) * gg[d] + bb[d];
}

// ------------------------- host launcher ------------------------------------
extern "C" void kernel_launch(void* const* d_in, const int* in_sizes, int n_in,
                              void* d_out, int out_size)
{
    const float* x     = (const float*)d_in[0];
    const float* pos_k = (const float*)d_in[1];
    const float* w1_k  = (const float*)d_in[2];
    const float* b1_k  = (const float*)d_in[3];
    const float* w2_k  = (const float*)d_in[4];
    const float* b2_k  = (const float*)d_in[5];
    const float* wa_k  = (const float*)d_in[6];
    const float* ba_k  = (const float*)d_in[7];
    const float* pos_q = (const float*)d_in[8];
    const float* w1_q  = (const float*)d_in[9];
    const float* b1_q  = (const float*)d_in[10];
    const float* w2_q  = (const float*)d_in[11];
    const float* b2_q  = (const float*)d_in[12];
    const float* wa_q  = (const float*)d_in[13];
    const float* ba_q  = (const float*)d_in[14];
    const float* wv    = (const float*)d_in[15];
    const float* bv    = (const float*)d_in[16];
    const float* ln_g  = (const float*)d_in[17];
    const float* ln_b  = (const float*)d_in[18];
    const float* wo    = (const float*)d_in[19];
    const float* bo    = (const float*)d_in[20];
    float* out = (float*)d_out;

    float *xa_k, *xa_q, *hk, *hq, *pk, *ak, *pq, *aq, *kk, *qq, *V, *G, *S, *Amat, *ret, *rn;
    cudaGetSymbolAddress((void**)&xa_k, g_xa_k);
    cudaGetSymbolAddress((void**)&xa_q, g_xa_q);
    cudaGetSymbolAddress((void**)&hk,   g_hk);
    cudaGetSymbolAddress((void**)&hq,   g_hq);
    cudaGetSymbolAddress((void**)&pk,   g_pk);
    cudaGetSymbolAddress((void**)&ak,   g_ak);
    cudaGetSymbolAddress((void**)&pq,   g_pq);
    cudaGetSymbolAddress((void**)&aq,   g_aq);
    cudaGetSymbolAddress((void**)&kk,   g_kk);
    cudaGetSymbolAddress((void**)&qq,   g_qq);
    cudaGetSymbolAddress((void**)&V,    g_V);
    cudaGetSymbolAddress((void**)&G,    g_G);
    cudaGetSymbolAddress((void**)&S,    g_S);
    cudaGetSymbolAddress((void**)&Amat, g_A);
    cudaGetSymbolAddress((void**)&ret,  g_ret);
    cudaGetSymbolAddress((void**)&rn,   g_rn);

    // 1. xa = x + pos (both encoders)
    addpos_kernel<<<(NTOK * Dd + 255) / 256, 256>>>(x, pos_k, pos_q);

    // 2. h = gelu(xa @ w1 + b1)   [2048,256]@[256,256]
    gemm_kernel<M_GELU, false, false><<<dim3(4, 32, 1), 256>>>(xa_k, w1_k, b1_k, nullptr, hk, NTOK, Dd, Dd, 0, 0, 0);
    gemm_kernel<M_GELU, false, false><<<dim3(4, 32, 1), 256>>>(xa_q, w1_q, b1_q, nullptr, hq, NTOK, Dd, Dd, 0, 0, 0);

    // 3. phase_raw = h @ w2 + b2, amp_raw = xa @ wa + ba   [2048,256]@[256,64]
    gemm_kernel<M_BIAS, false, false><<<dim3(1, 32, 1), 256>>>(hk,   w2_k, b2_k, nullptr, pk, NTOK, Kk, Dd, 0, 0, 0);
    gemm_kernel<M_BIAS, false, false><<<dim3(1, 32, 1), 256>>>(xa_k, wa_k, ba_k, nullptr, ak, NTOK, Kk, Dd, 0, 0, 0);
    gemm_kernel<M_BIAS, false, false><<<dim3(1, 32, 1), 256>>>(hq,   w2_q, b2_q, nullptr, pq, NTOK, Kk, Dd, 0, 0, 0);
    gemm_kernel<M_BIAS, false, false><<<dim3(1, 32, 1), 256>>>(xa_q, wa_q, ba_q, nullptr, aq, NTOK, Kk, Dd, 0, 0, 0);

    // 4. phasors -> feature maps kk/qq [NTOK, 128]
    phasor_kernel<<<(NTOK * Kk + 255) / 256, 256>>>(pk, ak, kk);
    phasor_kernel<<<(NTOK * Kk + 255) / 256, 256>>>(pq, aq, qq);

    // 5. V = x @ wv + bv
    gemm_kernel<M_BIAS, false, false><<<dim3(4, 32, 1), 256>>>(x, wv, bv, nullptr, V, NTOK, Dd, Dd, 0, 0, 0);

    // 6. per-chunk state: G[b,c] = KK_cᵀ @ V_c   (batched TN, 16 chunks)
    gemm_kernel<M_PLAIN, true, false><<<dim3(4, 2, NCH), 256>>>(
        kk, V, nullptr, nullptr, G, K2, Dd, CH,
        (long)CH * K2, (long)CH * Dd, (long)K2 * Dd);

    // 7. exclusive prefix over chunks -> S
    prefix_kernel<<<(Bb * K2 * Dd + 255) / 256, 256>>>();

    // 8. intra-chunk attention matrix A = tril(QQ_c @ KK_cᵀ)
    gemm_kernel<M_MASK, false, true><<<dim3(2, 2, NCH), 256>>>(
        qq, kk, nullptr, nullptr, Amat, CH, CH, K2,
        (long)CH * K2, (long)CH * K2, (long)CH * CH);

    // 9. ret_c = A_c @ V_c ; 10. ret_c += QQ_c @ S_c
    gemm_kernel<M_PLAIN, false, false><<<dim3(4, 2, NCH), 256>>>(
        Amat, V, nullptr, nullptr, ret, CH, Dd, CH,
        (long)CH * CH, (long)CH * Dd, (long)CH * Dd);
    gemm_kernel<M_ACC, false, false><<<dim3(4, 2, NCH), 256>>>(
        qq, S, nullptr, nullptr, ret, CH, Dd, K2,
        (long)CH * K2, (long)K2 * Dd, (long)CH * Dd);

    // 11. normalize + layernorm
    ln_kernel<<<NTOK, 256>>>(ret, ln_g, ln_b, rn);

    // 12. out = x + rn @ wo + bo
    gemm_kernel<M_RESID, false, false><<<dim3(4, 32, 1), 256>>>(rn, wo, bo, x, out, NTOK, Dd, Dd, 0, 0, 0);
}

// round 5
// speedup vs baseline: 1.7926x; 1.7926x over previous
#include <cuda_runtime.h>
#include <math.h>

#define Bb   2
#define Ll   1024
#define Dd   256
#define Kk   64
#define K2   128          // 2K (re|im concat)
#define NTOK (Bb*Ll)      // 2048
#define CH   128          // scan chunk length
#define NC   (Ll/CH)      // 8
#define NCH  (Bb*NC)      // 16
#define EPSv 1e-5f
#define PIv  3.14159265358979323846f

// ------------------------- scratch (static device memory) -------------------
__device__ float g_hk  [NTOK*Dd];
__device__ float g_hq  [NTOK*Dd];
__device__ float g_kk  [NTOK*K2];
__device__ float g_qq  [NTOK*K2];
__device__ float g_V   [NTOK*Dd];
__device__ float g_G   [NCH*K2*Dd];
__device__ float g_S   [NCH*K2*Dd];
__device__ float g_A   [NCH*CH*CH];
__device__ float g_ret [NTOK*Dd];
__device__ float g_rn  [NTOK*Dd];

// ------------------------- generic tiled SGEMM ------------------------------
// 64x64 block tile, 16 k-slice, 256 threads, 4x4 microtile. gridDim.z = batch.
enum { M_PLAIN = 0, M_MASK = 4, M_RESID = 5 };

template<int MODE, bool TA, bool TB>
__global__ void gemm_kernel(const float* __restrict__ A, const float* __restrict__ Bm,
                            const float* __restrict__ bias, const float* __restrict__ extra,
                            float* __restrict__ C,
                            int M, int N, int Kd,
                            long sA, long sB, long sC)
{
    A  += (long)blockIdx.z * sA;
    Bm += (long)blockIdx.z * sB;
    C  += (long)blockIdx.z * sC;
    if (MODE == M_RESID && extra) extra += (long)blockIdx.z * sC;

    __shared__ float As[16][65];
    __shared__ float Bs[16][65];

    const int tid = threadIdx.x;
    const int tr  = tid >> 4;
    const int tc  = tid & 15;
    const int rowTile = blockIdx.y * 64;
    const int colTile = blockIdx.x * 64;

    float acc[4][4] = {};

    for (int k0 = 0; k0 < Kd; k0 += 16) {
        #pragma unroll
        for (int t = 0; t < 4; t++) {
            int idx = tid + t * 256;
            int m = idx >> 4, k = idx & 15;
            As[k][m] = TA ? A[(long)(k0 + k) * M + rowTile + m]
                          : A[(long)(rowTile + m) * Kd + k0 + k];
        }
        #pragma unroll
        for (int t = 0; t < 4; t++) {
            int idx = tid + t * 256;
            if (!TB) {
                int k = idx >> 6, n = idx & 63;
                Bs[k][n] = Bm[(long)(k0 + k) * N + colTile + n];
            } else {
                int k = idx & 15, n = idx >> 4;
                Bs[k][n] = Bm[(long)(colTile + n) * Kd + k0 + k];
            }
        }
        __syncthreads();
        #pragma unroll
        for (int k = 0; k < 16; k++) {
            float a[4], b[4];
            #pragma unroll
            for (int i = 0; i < 4; i++) a[i] = As[k][tr + 16 * i];
            #pragma unroll
            for (int j = 0; j < 4; j++) b[j] = Bs[k][tc + 16 * j];
            #pragma unroll
            for (int i = 0; i < 4; i++)
                #pragma unroll
                for (int j = 0; j < 4; j++)
                    acc[i][j] = fmaf(a[i], b[j], acc[i][j]);
        }
        __syncthreads();
    }

    #pragma unroll
    for (int i = 0; i < 4; i++) {
        int r = rowTile + tr + 16 * i;
        #pragma unroll
        for (int j = 0; j < 4; j++) {
            int c = colTile + tc + 16 * j;
            float v = acc[i][j];
            if (MODE == M_RESID) v += bias[c];
            if (MODE == M_MASK) { if (c > r) v = 0.0f; }
            long o = (long)r * N + c;
            if (MODE == M_RESID) C[o] = extra[o] + v;
            else                 C[o] = v;
        }
    }
}

// ------------------------- encoder pre-GEMM (batched z=3) --------------------
// z=0: hk = gelu((x+pos_k)@w1_k + b1_k)
// z=1: hq = gelu((x+pos_q)@w1_q + b1_q)
// z=2: V  = x@wv + bv
__global__ void enc_gemm_kernel(const float* __restrict__ x,
                                const float* __restrict__ pos_k, const float* __restrict__ pos_q,
                                const float* __restrict__ w1_k, const float* __restrict__ b1_k,
                                const float* __restrict__ w1_q, const float* __restrict__ b1_q,
                                const float* __restrict__ wv,   const float* __restrict__ bv,
                                float* __restrict__ hk, float* __restrict__ hq, float* __restrict__ V)
{
    const int z = blockIdx.z;
    const float* W;  const float* bias; const float* pos; float* C;
    if (z == 0)      { W = w1_k; bias = b1_k; pos = pos_k; C = hk; }
    else if (z == 1) { W = w1_q; bias = b1_q; pos = pos_q; C = hq; }
    else             { W = wv;   bias = bv;   pos = nullptr; C = V; }

    __shared__ float As[16][65];
    __shared__ float Bs[16][65];

    const int tid = threadIdx.x;
    const int tr  = tid >> 4;
    const int tc  = tid & 15;
    const int rowTile = blockIdx.y * 64;
    const int colTile = blockIdx.x * 64;

    float acc[4][4] = {};

    for (int k0 = 0; k0 < Dd; k0 += 16) {
        #pragma unroll
        for (int t = 0; t < 4; t++) {
            int idx = tid + t * 256;
            int m = idx >> 4, k = idx & 15;
            int row = rowTile + m, col = k0 + k;
            float v = x[(long)row * Dd + col];
            if (pos) v += pos[(long)(row & (Ll - 1)) * Dd + col];
            As[k][m] = v;
        }
        #pragma unroll
        for (int t = 0; t < 4; t++) {
            int idx = tid + t * 256;
            int k = idx >> 6, n = idx & 63;
            Bs[k][n] = W[(long)(k0 + k) * Dd + colTile + n];
        }
        __syncthreads();
        #pragma unroll
        for (int k = 0; k < 16; k++) {
            float a[4], b[4];
            #pragma unroll
            for (int i = 0; i < 4; i++) a[i] = As[k][tr + 16 * i];
            #pragma unroll
            for (int j = 0; j < 4; j++) b[j] = Bs[k][tc + 16 * j];
            #pragma unroll
            for (int i = 0; i < 4; i++)
                #pragma unroll
                for (int j = 0; j < 4; j++)
                    acc[i][j] = fmaf(a[i], b[j], acc[i][j]);
        }
        __syncthreads();
    }

    #pragma unroll
    for (int i = 0; i < 4; i++) {
        int r = rowTile + tr + 16 * i;
        #pragma unroll
        for (int j = 0; j < 4; j++) {
            int c = colTile + tc + 16 * j;
            float v = acc[i][j] + bias[c];
            if (z < 2) v = 0.5f * v * (1.0f + erff(v * 0.70710678118654752440f));
            C[(long)r * Dd + c] = v;
        }
    }
}

// ------------------------- fused head GEMMs + phasor (batched z=2) -----------
// Per 32x64 tile computes BOTH phase_raw = h@w2+b2 and amp_raw = (x+pos)@wa+ba,
// then the phasor nonlinearity, writing kk/qq [NTOK, 2K] directly.
// z=0: k-branch (hk, pos_k, w2_k, wa_k -> kk);  z=1: q-branch -> qq.
__global__ void phasor_gemm_kernel(const float* __restrict__ x,
                                   const float* __restrict__ pos_k, const float* __restrict__ pos_q,
                                   const float* __restrict__ hk,   const float* __restrict__ hq,
                                   const float* __restrict__ w2_k, const float* __restrict__ b2_k,
                                   const float* __restrict__ wa_k, const float* __restrict__ ba_k,
                                   const float* __restrict__ w2_q, const float* __restrict__ b2_q,
                                   const float* __restrict__ wa_q, const float* __restrict__ ba_q,
                                   float* __restrict__ kk, float* __restrict__ qq)
{
    const int z = blockIdx.z;
    const float* h   = z ? hq    : hk;
    const float* pos = z ? pos_q : pos_k;
    const float* W2  = z ? w2_q  : w2_k;
    const float* B2  = z ? b2_q  : b2_k;
    const float* Wa  = z ? wa_q  : wa_k;
    const float* Ba  = z ? ba_q  : ba_k;
    float* out       = z ? qq    : kk;

    __shared__ float Ah[16][33];   // h tile        32 rows x 16 k
    __shared__ float Ax[16][33];   // (x+pos) tile
    __shared__ float Bp[16][65];   // w2 tile       16 k x 64 cols
    __shared__ float Ba_s[16][65]; // wa tile

    const int tid = threadIdx.x;
    const int tr  = tid >> 4;      // rows {tr, tr+16}
    const int tc  = tid & 15;      // cols {tc, tc+16, tc+32, tc+48}
    const int rowTile = blockIdx.y * 32;

    float accP[2][4] = {};
    float accA[2][4] = {};

    for (int k0 = 0; k0 < Dd; k0 += 16) {
        // A tiles: 32x16 = 512 elems, 2 per thread
        #pragma unroll
        for (int t = 0; t < 2; t++) {
            int idx = tid + t * 256;
            int m = idx >> 4, k = idx & 15;
            int row = rowTile + m, col = k0 + k;
            Ah[k][m] = h[(long)row * Dd + col];
            Ax[k][m] = x[(long)row * Dd + col] + pos[(long)(row & (Ll - 1)) * Dd + col];
        }
        // B tiles: 16x64 = 1024 elems, 4 per thread
        #pragma unroll
        for (int t = 0; t < 4; t++) {
            int idx = tid + t * 256;
            int k = idx >> 6, n = idx & 63;
            Bp[k][n]   = W2[(long)(k0 + k) * Kk + n];
            Ba_s[k][n] = Wa[(long)(k0 + k) * Kk + n];
        }
        __syncthreads();
        #pragma unroll
        for (int k = 0; k < 16; k++) {
            float ah[2], ax[2], bp[4], ba[4];
            #pragma unroll
            for (int i = 0; i < 2; i++) { ah[i] = Ah[k][tr + 16 * i]; ax[i] = Ax[k][tr + 16 * i]; }
            #pragma unroll
            for (int j = 0; j < 4; j++) { bp[j] = Bp[k][tc + 16 * j]; ba[j] = Ba_s[k][tc + 16 * j]; }
            #pragma unroll
            for (int i = 0; i < 2; i++)
                #pragma unroll
                for (int j = 0; j < 4; j++) {
                    accP[i][j] = fmaf(ah[i], bp[j], accP[i][j]);
                    accA[i][j] = fmaf(ax[i], ba[j], accA[i][j]);
                }
        }
        __syncthreads();
    }

    #pragma unroll
    for (int i = 0; i < 2; i++) {
        int n = rowTile + tr + 16 * i;   // token
        #pragma unroll
        for (int j = 0; j < 4; j++) {
            int c = tc + 16 * j;         // feature 0..63
            float p = accP[i][j] + B2[c];
            float a = accA[i][j] + Ba[c];
            float ph = tanhf(p) * PIv;
            float sp = fmaxf(a, 0.0f) + log1pf(expf(-fabsf(a)));
            float amp = sp + 0.1f;
            float s, cs;
            sincosf(ph, &s, &cs);
            out[(long)n * K2 + c]      = amp * cs;
            out[(long)n * K2 + Kk + c] = amp * s;
        }
    }
}

// ------------------------- fused retrieval GEMM: ret = A@V + QQ@S ------------
__global__ void ret_gemm_kernel(const float* __restrict__ Amat, const float* __restrict__ V,
                                const float* __restrict__ QQ,   const float* __restrict__ S,
                                float* __restrict__ ret)
{
    const int z = blockIdx.z;  // chunk
    const float* Ab = Amat + (long)z * CH * CH;
    const float* Vb = V    + (long)z * CH * Dd;
    const float* Qb = QQ   + (long)z * CH * K2;
    const float* Sb = S    + (long)z * K2 * Dd;
    float*       Cb = ret  + (long)z * CH * Dd;

    __shared__ float As[16][65];
    __shared__ float Bs[16][65];

    const int tid = threadIdx.x;
    const int tr  = tid >> 4;
    const int tc  = tid & 15;
    const int rowTile = blockIdx.y * 64;
    const int colTile = blockIdx.x * 64;

    float acc[4][4] = {};

    #pragma unroll 1
    for (int phase = 0; phase < 2; phase++) {
        const float* Ap = phase ? Qb : Ab;
        const float* Bp = phase ? Sb : Vb;
        const int lda   = phase ? K2 : CH;   // both 128, but keep explicit
        const int Kd    = phase ? K2 : CH;
        for (int k0 = 0; k0 < Kd; k0 += 16) {
            #pragma unroll
            for (int t = 0; t < 4; t++) {
                int idx = tid + t * 256;
                int m = idx >> 4, k = idx & 15;
                As[k][m] = Ap[(long)(rowTile + m) * lda + k0 + k];
            }
            #pragma unroll
            for (int t = 0; t < 4; t++) {
                int idx = tid + t * 256;
                int k = idx >> 6, n = idx & 63;
                Bs[k][n] = Bp[(long)(k0 + k) * Dd + colTile + n];
            }
            __syncthreads();
            #pragma unroll
            for (int k = 0; k < 16; k++) {
                float a[4], b[4];
                #pragma unroll
                for (int i = 0; i < 4; i++) a[i] = As[k][tr + 16 * i];
                #pragma unroll
                for (int j = 0; j < 4; j++) b[j] = Bs[k][tc + 16 * j];
                #pragma unroll
                for (int i = 0; i < 4; i++)
                    #pragma unroll
                    for (int j = 0; j < 4; j++)
                        acc[i][j] = fmaf(a[i], b[j], acc[i][j]);
            }
            __syncthreads();
        }
    }

    #pragma unroll
    for (int i = 0; i < 4; i++) {
        int r = rowTile + tr + 16 * i;
        #pragma unroll
        for (int j = 0; j < 4; j++) {
            int c = colTile + tc + 16 * j;
            Cb[(long)r * Dd + c] = acc[i][j];
        }
    }
}

// ------------------------- small kernels ------------------------------------
// exclusive prefix over the NC chunk states: S[b,c] = sum_{c'<c} G[b,c']
__global__ void prefix_kernel()
{
    const int KD = K2 * Dd;   // 32768
    int i = blockIdx.x * blockDim.x + threadIdx.x;
    if (i >= Bb * KD) return;
    int b = i / KD, r = i % KD;
    float acc = 0.0f;
    #pragma unroll
    for (int c = 0; c < NC; c++) {
        long o = ((long)(b * NC + c)) * KD + r;
        g_S[o] = acc;
        acc += g_G[o];
    }
}

// normalize by sqrt((l+1)*K), layernorm
__global__ void ln_kernel(const float* __restrict__ ret,
                          const float* __restrict__ gg,
                          const float* __restrict__ bb,
                          float* __restrict__ rn)
{
    int n = blockIdx.x;
    int l = n % Ll;
    int d = threadIdx.x;      // 256 threads == D
    float v = ret[(long)n * Dd + d] * rsqrtf((float)(l + 1) * (float)Kk);

    float s = v, s2 = v * v;
    #pragma unroll
    for (int o = 16; o; o >>= 1) {
        s  += __shfl_xor_sync(0xffffffffu, s,  o);
        s2 += __shfl_xor_sync(0xffffffffu, s2, o);
    }
    __shared__ float ss[8], ss2[8];
    int w = d >> 5, lane = d & 31;
    if (lane == 0) { ss[w] = s; ss2[w] = s2; }
    __syncthreads();
    if (w == 0) {
        float a  = (lane < 8) ? ss[lane]  : 0.0f;
        float a2 = (lane < 8) ? ss2[lane] : 0.0f;
        #pragma unroll
        for (int o = 4; o; o >>= 1) {
            a  += __shfl_xor_sync(0xffffffffu, a,  o);
            a2 += __shfl_xor_sync(0xffffffffu, a2, o);
        }
        if (lane == 0) { ss[0] = a; ss2[0] = a2; }
    }
    __syncthreads();
    float mu  = ss[0] / Dd;
    float var = ss2[0] / Dd - mu * mu;
    rn[(long)n * Dd + d] = (v - mu) * rsqrtf(var + EPSv) * gg[d] + bb[d];
}

// ------------------------- host launcher ------------------------------------
extern "C" void kernel_launch(void* const* d_in, const int* in_sizes, int n_in,
                              void* d_out, int out_size)
{
    const float* x     = (const float*)d_in[0];
    const float* pos_k = (const float*)d_in[1];
    const float* w1_k  = (const float*)d_in[2];
    const float* b1_k  = (const float*)d_in[3];
    const float* w2_k  = (const float*)d_in[4];
    const float* b2_k  = (const float*)d_in[5];
    const float* wa_k  = (const float*)d_in[6];
    const float* ba_k  = (const float*)d_in[7];
    const float* pos_q = (const float*)d_in[8];
    const float* w1_q  = (const float*)d_in[9];
    const float* b1_q  = (const float*)d_in[10];
    const float* w2_q  = (const float*)d_in[11];
    const float* b2_q  = (const float*)d_in[12];
    const float* wa_q  = (const float*)d_in[13];
    const float* ba_q  = (const float*)d_in[14];
    const float* wv    = (const float*)d_in[15];
    const float* bv    = (const float*)d_in[16];
    const float* ln_g  = (const float*)d_in[17];
    const float* ln_b  = (const float*)d_in[18];
    const float* wo    = (const float*)d_in[19];
    const float* bo    = (const float*)d_in[20];
    float* out = (float*)d_out;

    float *hk, *hq, *kk, *qq, *V, *G, *S, *Amat, *ret, *rn;
    cudaGetSymbolAddress((void**)&hk,   g_hk);
    cudaGetSymbolAddress((void**)&hq,   g_hq);
    cudaGetSymbolAddress((void**)&kk,   g_kk);
    cudaGetSymbolAddress((void**)&qq,   g_qq);
    cudaGetSymbolAddress((void**)&V,    g_V);
    cudaGetSymbolAddress((void**)&G,    g_G);
    cudaGetSymbolAddress((void**)&S,    g_S);
    cudaGetSymbolAddress((void**)&Amat, g_A);
    cudaGetSymbolAddress((void**)&ret,  g_ret);
    cudaGetSymbolAddress((void**)&rn,   g_rn);

    // 1. hk = gelu((x+pos_k)@w1_k+b1), hq likewise, V = x@wv+bv  (one launch, z=3)
    enc_gemm_kernel<<<dim3(4, 32, 3), 256>>>(x, pos_k, pos_q,
                                             w1_k, b1_k, w1_q, b1_q, wv, bv,
                                             hk, hq, V);

    // 2. fused head GEMMs + phasor -> kk, qq  (one launch, z=2, 128 CTAs)
    phasor_gemm_kernel<<<dim3(1, 64, 2), 256>>>(x, pos_k, pos_q, hk, hq,
                                                w2_k, b2_k, wa_k, ba_k,
                                                w2_q, b2_q, wa_q, ba_q,
                                                kk, qq);

    // 3. per-chunk state: G[c] = KK_c^T @ V_c  (batched TN, 16 chunks)
    gemm_kernel<M_PLAIN, true, false><<<dim3(4, 2, NCH), 256>>>(
        kk, V, nullptr, nullptr, G, K2, Dd, CH,
        (long)CH * K2, (long)CH * Dd, (long)K2 * Dd);

    // 4. exclusive prefix over chunks -> S
    prefix_kernel<<<(Bb * K2 * Dd + 255) / 256, 256>>>();

    // 5. intra-chunk attention matrix A = tril(QQ_c @ KK_c^T)
    gemm_kernel<M_MASK, false, true><<<dim3(2, 2, NCH), 256>>>(
        qq, kk, nullptr, nullptr, Amat, CH, CH, K2,
        (long)CH * K2, (long)CH * K2, (long)CH * CH);

    // 6. ret_c = A_c @ V_c + QQ_c @ S_c  (fused dual GEMM)
    ret_gemm_kernel<<<dim3(4, 2, NCH), 256>>>(Amat, V, qq, S, ret);

    // 7. normalize + layernorm
    ln_kernel<<<NTOK, 256>>>(ret, ln_g, ln_b, rn);

    // 8. out = x + rn @ wo + bo
    gemm_kernel<M_RESID, false, false><<<dim3(4, 32, 1), 256>>>(rn, wo, bo, x, out, NTOK, Dd, Dd, 0, 0, 0);
}

// round 7
// speedup vs baseline: 2.3326x; 1.3013x over previous
#include <cuda_runtime.h>
#include <math.h>

#define Bb   2
#define Ll   1024
#define Dd   256
#define Kk   64
#define K2   128          // 2K (re|im concat)
#define NTOK (Bb*Ll)      // 2048
#define CH   128          // scan chunk length
#define NC   (Ll/CH)      // 8
#define NCH  (Bb*NC)      // 16
#define EPSv 1e-5f
#define PIv  3.14159265358979323846f

// ------------------------- scratch (static device memory) -------------------
__device__ float g_hk  [NTOK*Dd];
__device__ float g_hq  [NTOK*Dd];
__device__ float g_kk  [NTOK*K2];
__device__ float g_qq  [NTOK*K2];
__device__ float g_V   [NTOK*Dd];
__device__ float g_G   [NCH*K2*Dd];
__device__ float g_S   [NCH*K2*Dd];
__device__ float g_A   [NCH*CH*CH];
__device__ float g_ret [NTOK*Dd];
__device__ float g_rn  [NTOK*Dd];

// ------------------------- generic tiled SGEMM (vectorized) ------------------
// 64x64 block tile, 16 k-slice, 256 threads.
// Microtile: thread (tr=tid>>4, tc=tid&15) owns rows rowTile+tr*4..+3,
// cols colTile+tc*4..+3  -> fragments are contiguous float4 LDS.128 loads.
enum { M_PLAIN = 0, M_MASK = 4, M_RESID = 5 };

template<int MODE, bool TA, bool TB>
__global__ void gemm_kernel(const float* __restrict__ A, const float* __restrict__ Bm,
                            const float* __restrict__ bias, const float* __restrict__ extra,
                            float* __restrict__ C,
                            int M, int N, int Kd,
                            long sA, long sB, long sC)
{
    A  += (long)blockIdx.z * sA;
    Bm += (long)blockIdx.z * sB;
    C  += (long)blockIdx.z * sC;
    if (MODE == M_RESID && extra) extra += (long)blockIdx.z * sC;

    __shared__ __align__(16) float As[16][68];
    __shared__ __align__(16) float Bs[16][68];

    const int tid = threadIdx.x;
    const int tr  = tid >> 4;              // 0..15
    const int tc  = tid & 15;              // 0..15
    const int rowTile = blockIdx.y * 64;
    const int colTile = blockIdx.x * 64;

    float acc[4][4] = {};

    for (int k0 = 0; k0 < Kd; k0 += 16) {
        // ---- load A tile (64 x 16) ----
        if (!TA) {
            // A[row][k], k contiguous: float4 along k, transpose into As
            int m  = tid >> 2;             // 0..63
            int kq = (tid & 3) * 4;        // 0,4,8,12
            float4 v = *(const float4*)&A[(long)(rowTile + m) * Kd + k0 + kq];
            As[kq + 0][m] = v.x; As[kq + 1][m] = v.y;
            As[kq + 2][m] = v.z; As[kq + 3][m] = v.w;
        } else {
            // A[k][m], m contiguous: direct float4 store
            int k  = tid >> 4;             // 0..15
            int mq = (tid & 15) * 4;       // 0..60
            float4 v = *(const float4*)&A[(long)(k0 + k) * M + rowTile + mq];
            *(float4*)&As[k][mq] = v;
        }
        // ---- load B tile (16 x 64) ----
        if (!TB) {
            int k  = tid >> 4;
            int nq = (tid & 15) * 4;
            float4 v = *(const float4*)&Bm[(long)(k0 + k) * N + colTile + nq];
            *(float4*)&Bs[k][nq] = v;
        } else {
            // B[n][k], k contiguous: transpose into Bs
            int n  = tid >> 2;             // 0..63
            int kq = (tid & 3) * 4;
            float4 v = *(const float4*)&Bm[(long)(colTile + n) * Kd + k0 + kq];
            Bs[kq + 0][n] = v.x; Bs[kq + 1][n] = v.y;
            Bs[kq + 2][n] = v.z; Bs[kq + 3][n] = v.w;
        }
        __syncthreads();
        #pragma unroll
        for (int k = 0; k < 16; k++) {
            float4 a = *(const float4*)&As[k][tr * 4];
            float4 b = *(const float4*)&Bs[k][tc * 4];
            float av[4] = {a.x, a.y, a.z, a.w};
            float bv[4] = {b.x, b.y, b.z, b.w};
            #pragma unroll
            for (int i = 0; i < 4; i++)
                #pragma unroll
                for (int j = 0; j < 4; j++)
                    acc[i][j] = fmaf(av[i], bv[j], acc[i][j]);
        }
        __syncthreads();
    }

    #pragma unroll
    for (int i = 0; i < 4; i++) {
        int r = rowTile + tr * 4 + i;
        int c0 = colTile + tc * 4;
        float4 v = make_float4(acc[i][0], acc[i][1], acc[i][2], acc[i][3]);
        if (MODE == M_RESID) {
            float4 bi = *(const float4*)&bias[c0];
            float4 ex = *(const float4*)&extra[(long)r * N + c0];
            v.x += bi.x + ex.x; v.y += bi.y + ex.y;
            v.z += bi.z + ex.z; v.w += bi.w + ex.w;
        }
        if (MODE == M_MASK) {
            if (c0 + 0 > r) v.x = 0.0f;
            if (c0 + 1 > r) v.y = 0.0f;
            if (c0 + 2 > r) v.z = 0.0f;
            if (c0 + 3 > r) v.w = 0.0f;
        }
        *(float4*)&C[(long)r * N + c0] = v;
    }
}

// ------------------------- encoder pre-GEMM (batched z=3) --------------------
// z=0: hk = gelu((x+pos_k)@w1_k + b1_k)
// z=1: hq = gelu((x+pos_q)@w1_q + b1_q)
// z=2: V  = x@wv + bv
__global__ void enc_gemm_kernel(const float* __restrict__ x,
                                const float* __restrict__ pos_k, const float* __restrict__ pos_q,
                                const float* __restrict__ w1_k, const float* __restrict__ b1_k,
                                const float* __restrict__ w1_q, const float* __restrict__ b1_q,
                                const float* __restrict__ wv,   const float* __restrict__ bv,
                                float* __restrict__ hk, float* __restrict__ hq, float* __restrict__ V)
{
    const int z = blockIdx.z;
    const float* W;  const float* bias; const float* pos; float* C;
    if (z == 0)      { W = w1_k; bias = b1_k; pos = pos_k; C = hk; }
    else if (z == 1) { W = w1_q; bias = b1_q; pos = pos_q; C = hq; }
    else             { W = wv;   bias = bv;   pos = nullptr; C = V; }

    __shared__ __align__(16) float As[16][68];
    __shared__ __align__(16) float Bs[16][68];

    const int tid = threadIdx.x;
    const int tr  = tid >> 4;
    const int tc  = tid & 15;
    const int rowTile = blockIdx.y * 64;
    const int colTile = blockIdx.x * 64;

    float acc[4][4] = {};

    for (int k0 = 0; k0 < Dd; k0 += 16) {
        {
            int m  = tid >> 2;
            int kq = (tid & 3) * 4;
            int row = rowTile + m;
            float4 v = *(const float4*)&x[(long)row * Dd + k0 + kq];
            if (pos) {
                float4 p = *(const float4*)&pos[(long)(row & (Ll - 1)) * Dd + k0 + kq];
                v.x += p.x; v.y += p.y; v.z += p.z; v.w += p.w;
            }
            As[kq + 0][m] = v.x; As[kq + 1][m] = v.y;
            As[kq + 2][m] = v.z; As[kq + 3][m] = v.w;
        }
        {
            int k  = tid >> 4;
            int nq = (tid & 15) * 4;
            float4 v = *(const float4*)&W[(long)(k0 + k) * Dd + colTile + nq];
            *(float4*)&Bs[k][nq] = v;
        }
        __syncthreads();
        #pragma unroll
        for (int k = 0; k < 16; k++) {
            float4 a = *(const float4*)&As[k][tr * 4];
            float4 b = *(const float4*)&Bs[k][tc * 4];
            float av[4] = {a.x, a.y, a.z, a.w};
            float bv_[4] = {b.x, b.y, b.z, b.w};
            #pragma unroll
            for (int i = 0; i < 4; i++)
                #pragma unroll
                for (int j = 0; j < 4; j++)
                    acc[i][j] = fmaf(av[i], bv_[j], acc[i][j]);
        }
        __syncthreads();
    }

    int c0 = colTile + tc * 4;
    float4 bi = *(const float4*)&bias[c0];
    #pragma unroll
    for (int i = 0; i < 4; i++) {
        int r = rowTile + tr * 4 + i;
        float4 v = make_float4(acc[i][0] + bi.x, acc[i][1] + bi.y,
                               acc[i][2] + bi.z, acc[i][3] + bi.w);
        if (z < 2) {
            v.x = 0.5f * v.x * (1.0f + erff(v.x * 0.70710678118654752440f));
            v.y = 0.5f * v.y * (1.0f + erff(v.y * 0.70710678118654752440f));
            v.z = 0.5f * v.z * (1.0f + erff(v.z * 0.70710678118654752440f));
            v.w = 0.5f * v.w * (1.0f + erff(v.w * 0.70710678118654752440f));
        }
        *(float4*)&C[(long)r * Dd + c0] = v;
    }
}

// ------------------------- fused head GEMMs + phasor (batched z=2) -----------
// Per 32x64 tile computes BOTH phase_raw = h@w2+b2 and amp_raw = (x+pos)@wa+ba,
// then the phasor nonlinearity, writing kk/qq [NTOK, 2K] directly.
__global__ void phasor_gemm_kernel(const float* __restrict__ x,
                                   const float* __restrict__ pos_k, const float* __restrict__ pos_q,
                                   const float* __restrict__ hk,   const float* __restrict__ hq,
                                   const float* __restrict__ w2_k, const float* __restrict__ b2_k,
                                   const float* __restrict__ wa_k, const float* __restrict__ ba_k,
                                   const float* __restrict__ w2_q, const float* __restrict__ b2_q,
                                   const float* __restrict__ wa_q, const float* __restrict__ ba_q,
                                   float* __restrict__ kk, float* __restrict__ qq)
{
    const int z = blockIdx.z;
    const float* h   = z ? hq    : hk;
    const float* pos = z ? pos_q : pos_k;
    const float* W2  = z ? w2_q  : w2_k;
    const float* B2  = z ? b2_q  : b2_k;
    const float* Wa  = z ? wa_q  : wa_k;
    const float* Ba  = z ? ba_q  : ba_k;
    float* out       = z ? qq    : kk;

    __shared__ __align__(16) float Ah[16][36];   // 32 rows
    __shared__ __align__(16) float Ax[16][36];
    __shared__ __align__(16) float Bp[16][68];   // 64 cols
    __shared__ __align__(16) float Bas[16][68];

    const int tid = threadIdx.x;
    const int tr  = tid >> 4;      // rows tr*2..+1
    const int tc  = tid & 15;      // cols tc*4..+3
    const int rowTile = blockIdx.y * 32;

    float accP[2][4] = {};
    float accA[2][4] = {};

    for (int k0 = 0; k0 < Dd; k0 += 16) {
        // A tiles: 32x16 = 512 elems, float2 along k per thread
        {
            int m  = tid >> 3;          // 0..31
            int kq = (tid & 7) * 2;     // 0..14
            int row = rowTile + m;
            float2 vh = *(const float2*)&h[(long)row * Dd + k0 + kq];
            float2 vx = *(const float2*)&x[(long)row * Dd + k0 + kq];
            float2 vp = *(const float2*)&pos[(long)(row & (Ll - 1)) * Dd + k0 + kq];
            Ah[kq + 0][m] = vh.x;        Ah[kq + 1][m] = vh.y;
            Ax[kq + 0][m] = vx.x + vp.x; Ax[kq + 1][m] = vx.y + vp.y;
        }
        // B tiles: 16x64, float4 along n
        {
            int k  = tid >> 4;
            int nq = (tid & 15) * 4;
            *(float4*)&Bp[k][nq]  = *(const float4*)&W2[(long)(k0 + k) * Kk + nq];
            *(float4*)&Bas[k][nq] = *(const float4*)&Wa[(long)(k0 + k) * Kk + nq];
        }
        __syncthreads();
        #pragma unroll
        for (int k = 0; k < 16; k++) {
            float2 ah = *(const float2*)&Ah[k][tr * 2];
            float2 ax = *(const float2*)&Ax[k][tr * 2];
            float4 bp = *(const float4*)&Bp[k][tc * 4];
            float4 ba = *(const float4*)&Bas[k][tc * 4];
            float ahv[2] = {ah.x, ah.y}, axv[2] = {ax.x, ax.y};
            float bpv[4] = {bp.x, bp.y, bp.z, bp.w};
            float bav[4] = {ba.x, ba.y, ba.z, ba.w};
            #pragma unroll
            for (int i = 0; i < 2; i++)
                #pragma unroll
                for (int j = 0; j < 4; j++) {
                    accP[i][j] = fmaf(ahv[i], bpv[j], accP[i][j]);
                    accA[i][j] = fmaf(axv[i], bav[j], accA[i][j]);
                }
        }
        __syncthreads();
    }

    int c0 = tc * 4;
    float4 b2v = *(const float4*)&B2[c0];
    float4 bav = *(const float4*)&Ba[c0];
    #pragma unroll
    for (int i = 0; i < 2; i++) {
        int n = rowTile + tr * 2 + i;
        float4 oc, os;
        float b2a[4] = {b2v.x, b2v.y, b2v.z, b2v.w};
        float baa[4] = {bav.x, bav.y, bav.z, bav.w};
        float cvals[4], svals[4];
        #pragma unroll
        for (int j = 0; j < 4; j++) {
            float p = accP[i][j] + b2a[j];
            float a = accA[i][j] + baa[j];
            float ph = tanhf(p) * PIv;
            float sp = fmaxf(a, 0.0f) + log1pf(expf(-fabsf(a)));
            float amp = sp + 0.1f;
            float s, cs;
            sincosf(ph, &s, &cs);
            cvals[j] = amp * cs;
            svals[j] = amp * s;
        }
        oc = make_float4(cvals[0], cvals[1], cvals[2], cvals[3]);
        os = make_float4(svals[0], svals[1], svals[2], svals[3]);
        *(float4*)&out[(long)n * K2 + c0]      = oc;
        *(float4*)&out[(long)n * K2 + Kk + c0] = os;
    }
}

// ------------------------- fused retrieval GEMM: ret = A@V + QQ@S ------------
__global__ void ret_gemm_kernel(const float* __restrict__ Amat, const float* __restrict__ V,
                                const float* __restrict__ QQ,   const float* __restrict__ S,
                                float* __restrict__ ret)
{
    const int z = blockIdx.z;  // chunk
    const float* Ab = Amat + (long)z * CH * CH;
    const float* Vb = V    + (long)z * CH * Dd;
    const float* Qb = QQ   + (long)z * CH * K2;
    const float* Sb = S    + (long)z * K2 * Dd;
    float*       Cb = ret  + (long)z * CH * Dd;

    __shared__ __align__(16) float As[16][68];
    __shared__ __align__(16) float Bs[16][68];

    const int tid = threadIdx.x;
    const int tr  = tid >> 4;
    const int tc  = tid & 15;
    const int rowTile = blockIdx.y * 64;
    const int colTile = blockIdx.x * 64;

    float acc[4][4] = {};

    #pragma unroll 1
    for (int phase = 0; phase < 2; phase++) {
        const float* Ap = phase ? Qb : Ab;    // both lda = 128
        const float* Bp = phase ? Sb : Vb;    // both ldb = 256
        for (int k0 = 0; k0 < 128; k0 += 16) {
            {
                int m  = tid >> 2;
                int kq = (tid & 3) * 4;
                float4 v = *(const float4*)&Ap[(long)(rowTile + m) * 128 + k0 + kq];
                As[kq + 0][m] = v.x; As[kq + 1][m] = v.y;
                As[kq + 2][m] = v.z; As[kq + 3][m] = v.w;
            }
            {
                int k  = tid >> 4;
                int nq = (tid & 15) * 4;
                *(float4*)&Bs[k][nq] = *(const float4*)&Bp[(long)(k0 + k) * Dd + colTile + nq];
            }
            __syncthreads();
            #pragma unroll
            for (int k = 0; k < 16; k++) {
                float4 a = *(const float4*)&As[k][tr * 4];
                float4 b = *(const float4*)&Bs[k][tc * 4];
                float av[4] = {a.x, a.y, a.z, a.w};
                float bv[4] = {b.x, b.y, b.z, b.w};
                #pragma unroll
                for (int i = 0; i < 4; i++)
                    #pragma unroll
                    for (int j = 0; j < 4; j++)
                        acc[i][j] = fmaf(av[i], bv[j], acc[i][j]);
            }
            __syncthreads();
        }
    }

    #pragma unroll
    for (int i = 0; i < 4; i++) {
        int r = rowTile + tr * 4 + i;
        int c0 = colTile + tc * 4;
        *(float4*)&Cb[(long)r * Dd + c0] =
            make_float4(acc[i][0], acc[i][1], acc[i][2], acc[i][3]);
    }
}

// ------------------------- small kernels ------------------------------------
// exclusive prefix over the NC chunk states: S[b,c] = sum_{c'<c} G[b,c']
// float4 + all-loads-first (MLP=8)
__global__ void prefix_kernel()
{
    const int KD4 = K2 * Dd / 4;   // 8192 float4 per chunk state
    int i = blockIdx.x * blockDim.x + threadIdx.x;
    if (i >= Bb * KD4) return;
    int b = i / KD4, r = i % KD4;
    const float4* G4 = reinterpret_cast<const float4*>(g_G);
    float4*       S4 = reinterpret_cast<float4*>(g_S);

    float4 g[NC];
    #pragma unroll
    for (int c = 0; c < NC; c++)
        g[c] = G4[(long)(b * NC + c) * KD4 + r];

    float4 acc = make_float4(0.f, 0.f, 0.f, 0.f);
    #pragma unroll
    for (int c = 0; c < NC; c++) {
        S4[(long)(b * NC + c) * KD4 + r] = acc;
        acc.x += g[c].x; acc.y += g[c].y;
        acc.z += g[c].z; acc.w += g[c].w;
    }
}

// normalize by sqrt((l+1)*K), layernorm
__global__ void ln_kernel(const float* __restrict__ ret,
                          const float* __restrict__ gg,
                          const float* __restrict__ bb,
                          float* __restrict__ rn)
{
    int n = blockIdx.x;
    int l = n % Ll;
    int d = threadIdx.x;      // 256 threads == D
    float v = ret[(long)n * Dd + d] * rsqrtf((float)(l + 1) * (float)Kk);

    float s = v, s2 = v * v;
    #pragma unroll
    for (int o = 16; o; o >>= 1) {
        s  += __shfl_xor_sync(0xffffffffu, s,  o);
        s2 += __shfl_xor_sync(0xffffffffu, s2, o);
    }
    __shared__ float ss[8], ss2[8];
    int w = d >> 5, lane = d & 31;
    if (lane == 0) { ss[w] = s; ss2[w] = s2; }
    __syncthreads();
    if (w == 0) {
        float a  = (lane < 8) ? ss[lane]  : 0.0f;
        float a2 = (lane < 8) ? ss2[lane] : 0.0f;
        #pragma unroll
        for (int o = 4; o; o >>= 1) {
            a  += __shfl_xor_sync(0xffffffffu, a,  o);
            a2 += __shfl_xor_sync(0xffffffffu, a2, o);
        }
        if (lane == 0) { ss[0] = a; ss2[0] = a2; }
    }
    __syncthreads();
    float mu  = ss[0] / Dd;
    float var = ss2[0] / Dd - mu * mu;
    rn[(long)n * Dd + d] = (v - mu) * rsqrtf(var + EPSv) * gg[d] + bb[d];
}

// ------------------------- host launcher ------------------------------------
extern "C" void kernel_launch(void* const* d_in, const int* in_sizes, int n_in,
                              void* d_out, int out_size)
{
    const float* x     = (const float*)d_in[0];
    const float* pos_k = (const float*)d_in[1];
    const float* w1_k  = (const float*)d_in[2];
    const float* b1_k  = (const float*)d_in[3];
    const float* w2_k  = (const float*)d_in[4];
    const float* b2_k  = (const float*)d_in[5];
    const float* wa_k  = (const float*)d_in[6];
    const float* ba_k  = (const float*)d_in[7];
    const float* pos_q = (const float*)d_in[8];
    const float* w1_q  = (const float*)d_in[9];
    const float* b1_q  = (const float*)d_in[10];
    const float* w2_q  = (const float*)d_in[11];
    const float* b2_q  = (const float*)d_in[12];
    const float* wa_q  = (const float*)d_in[13];
    const float* ba_q  = (const float*)d_in[14];
    const float* wv    = (const float*)d_in[15];
    const float* bv    = (const float*)d_in[16];
    const float* ln_g  = (const float*)d_in[17];
    const float* ln_b  = (const float*)d_in[18];
    const float* wo    = (const float*)d_in[19];
    const float* bo    = (const float*)d_in[20];
    float* out = (float*)d_out;

    float *hk, *hq, *kk, *qq, *V, *G, *S, *Amat, *ret, *rn;
    cudaGetSymbolAddress((void**)&hk,   g_hk);
    cudaGetSymbolAddress((void**)&hq,   g_hq);
    cudaGetSymbolAddress((void**)&kk,   g_kk);
    cudaGetSymbolAddress((void**)&qq,   g_qq);
    cudaGetSymbolAddress((void**)&V,    g_V);
    cudaGetSymbolAddress((void**)&G,    g_G);
    cudaGetSymbolAddress((void**)&S,    g_S);
    cudaGetSymbolAddress((void**)&Amat, g_A);
    cudaGetSymbolAddress((void**)&ret,  g_ret);
    cudaGetSymbolAddress((void**)&rn,   g_rn);

    // 1. hk = gelu((x+pos_k)@w1_k+b1), hq likewise, V = x@wv+bv  (z=3)
    enc_gemm_kernel<<<dim3(4, 32, 3), 256>>>(x, pos_k, pos_q,
                                             w1_k, b1_k, w1_q, b1_q, wv, bv,
                                             hk, hq, V);

    // 2. fused head GEMMs + phasor -> kk, qq  (z=2, 128 CTAs)
    phasor_gemm_kernel<<<dim3(1, 64, 2), 256>>>(x, pos_k, pos_q, hk, hq,
                                                w2_k, b2_k, wa_k, ba_k,
                                                w2_q, b2_q, wa_q, ba_q,
                                                kk, qq);

    // 3. per-chunk state: G[c] = KK_c^T @ V_c  (batched TN, 16 chunks)
    gemm_kernel<M_PLAIN, true, false><<<dim3(4, 2, NCH), 256>>>(
        kk, V, nullptr, nullptr, G, K2, Dd, CH,
        (long)CH * K2, (long)CH * Dd, (long)K2 * Dd);

    // 4. exclusive prefix over chunks -> S
    prefix_kernel<<<(Bb * K2 * Dd / 4 + 255) / 256, 256>>>();

    // 5. intra-chunk attention matrix A = tril(QQ_c @ KK_c^T)
    gemm_kernel<M_MASK, false, true><<<dim3(2, 2, NCH), 256>>>(
        qq, kk, nullptr, nullptr, Amat, CH, CH, K2,
        (long)CH * K2, (long)CH * K2, (long)CH * CH);

    // 6. ret_c = A_c @ V_c + QQ_c @ S_c  (fused dual GEMM)
    ret_gemm_kernel<<<dim3(4, 2, NCH), 256>>>(Amat, V, qq, S, ret);

    // 7. normalize + layernorm
    ln_kernel<<<NTOK, 256>>>(ret, ln_g, ln_b, rn);

    // 8. out = x + rn @ wo + bo
    gemm_kernel<M_RESID, false, false><<<dim3(4, 32, 1), 256>>>(rn, wo, bo, x, out, NTOK, Dd, Dd, 0, 0, 0);
}